// round 8
// baseline (speedup 1.0000x reference)
#include <cuda_runtime.h>
#include <math.h>

#define BB   2
#define TT   1024
#define HH   1024
#define NHD  16
#define NKVH 4
#define HDD  64
#define NE   64
#define TOPK 8
#define NI   512
#define NTOK (BB*TT)   // 2048

typedef unsigned long long ull;

__device__ __forceinline__ ull pk2(float a, float b) {
    ull r; asm("mov.b64 %0,{%1,%2};" : "=l"(r) : "f"(a), "f"(b)); return r;
}
__device__ __forceinline__ void fma2(ull& d, ull a, ull b) {
    asm("fma.rn.f32x2 %0,%1,%2,%0;" : "+l"(d) : "l"(a), "l"(b));
}
__device__ __forceinline__ void mul2(ull& d, ull a) {
    asm("mul.rn.f32x2 %0,%0,%1;" : "+l"(d) : "l"(a), "l"(a));
}
__device__ __forceinline__ float2 up2(ull v) {
    float2 f; asm("mov.b64 {%0,%1},%2;" : "=f"(f.x), "=f"(f.y) : "l"(v)); return f;
}

// ---------------- scratch (device globals) ----------
__device__ float g_h  [NTOK*HH];
__device__ float g_q  [NTOK*NHD*HDD];
__device__ float g_k  [NTOK*NKVH*HDD];
__device__ float g_v  [NTOK*NKVH*HDD];
__device__ float g_att[NTOK*NHD*HDD];
__device__ float g_f  [NTOK*HH];
__device__ float g_y  [(size_t)NTOK*TOPK*HH];
__device__ int   g_cnt[NE];
__device__ int   g_tok[NE*NTOK];
__device__ float g_scr[NE*NTOK];
__device__ int   g_slt[NE*NTOK];

// ---------------- rmsnorm ----------------
__global__ void rmsnorm_k(const float* __restrict__ x, const float* __restrict__ w,
                          float* __restrict__ o) {
    int row = blockIdx.x;
    const float* xr = x + (size_t)row * HH;
    float ss = 0.f;
    for (int i = threadIdx.x; i < HH; i += 256) { float v = xr[i]; ss += v * v; }
    __shared__ float red[256];
    red[threadIdx.x] = ss; __syncthreads();
    for (int s = 128; s > 0; s >>= 1) {
        if (threadIdx.x < s) red[threadIdx.x] += red[threadIdx.x + s];
        __syncthreads();
    }
    float inv = rsqrtf(red[0] * (1.0f / HH) + 1e-6f);
    float* op = o + (size_t)row * HH;
    for (int i = threadIdx.x; i < HH; i += 256) op[i] = xr[i] * inv * w[i];
}

// ======== 128x128 register-tiled SGEMM core (8m x 8n per thread) ========
// As[k][m] un-duplicated; splats packed in regs. 32 FMA2 per k per thread.
struct Tile128 {
    float (*As)[128];
    float (*Bs)[128];
};

__device__ __forceinline__ void gemm128_body(
    const float* __restrict__ Ab, const float* __restrict__ Bb,
    int K, int N, float As[16][128], float Bs[16][128],
    ull acc[8][4], int tid)
{
    int tx = tid & 15, ty = tid >> 4;         // tx: n-group, ty: m-group
    int ar = tid >> 1, ac = (tid & 1) * 8;    // A load: row, k-offset
    int br = tid >> 4, bc = (tid & 15) * 8;   // B load

    for (int k0 = 0; k0 < K; k0 += 16) {
        float4 a0 = *(const float4*)(Ab + (size_t)ar * K + k0 + ac);
        float4 a1 = *(const float4*)(Ab + (size_t)ar * K + k0 + ac + 4);
        float4 b0 = *(const float4*)(Bb + (size_t)(k0 + br) * N + bc);
        float4 b1 = *(const float4*)(Bb + (size_t)(k0 + br) * N + bc + 4);
        __syncthreads();
        As[ac + 0][ar] = a0.x; As[ac + 1][ar] = a0.y;
        As[ac + 2][ar] = a0.z; As[ac + 3][ar] = a0.w;
        As[ac + 4][ar] = a1.x; As[ac + 5][ar] = a1.y;
        As[ac + 6][ar] = a1.z; As[ac + 7][ar] = a1.w;
        *(float4*)&Bs[br][bc]     = b0;
        *(float4*)&Bs[br][bc + 4] = b1;
        __syncthreads();
        #pragma unroll
        for (int k = 0; k < 16; k++) {
            float4 f0 = *(const float4*)&As[k][ty * 8];
            float4 f1 = *(const float4*)&As[k][ty * 8 + 4];
            ull s0 = pk2(f0.x, f0.x), s1 = pk2(f0.y, f0.y);
            ull s2 = pk2(f0.z, f0.z), s3 = pk2(f0.w, f0.w);
            ull s4 = pk2(f1.x, f1.x), s5 = pk2(f1.y, f1.y);
            ull s6 = pk2(f1.z, f1.z), s7 = pk2(f1.w, f1.w);
            const ull* bp = (const ull*)&Bs[k][tx * 8];
            ull w0 = bp[0], w1 = bp[1], w2 = bp[2], w3 = bp[3];
            #define ROW(i, s) fma2(acc[i][0], s, w0); fma2(acc[i][1], s, w1); \
                              fma2(acc[i][2], s, w2); fma2(acc[i][3], s, w3);
            ROW(0, s0) ROW(1, s1) ROW(2, s2) ROW(3, s3)
            ROW(4, s4) ROW(5, s5) ROW(6, s6) ROW(7, s7)
            #undef ROW
        }
    }
}

// ---------------- generic SGEMM (M,N mult of 128, K mult of 16), C=A@B(+R) --
__global__ __launch_bounds__(256)
void sgemm2_k(const float* __restrict__ A, const float* __restrict__ B,
              const float* __restrict__ R, float* __restrict__ C,
              int N, int K) {
    __shared__ float As[16][128];
    __shared__ float Bs[16][128];
    int tid = threadIdx.x;
    int tx = tid & 15, ty = tid >> 4;
    const float* Ab = A + (size_t)blockIdx.y * 128 * K;
    const float* Bb = B + (size_t)blockIdx.x * 128;
    ull acc[8][4];
    #pragma unroll
    for (int i = 0; i < 8; i++)
        #pragma unroll
        for (int j = 0; j < 4; j++) acc[i][j] = 0ull;

    gemm128_body(Ab, Bb, K, N, As, Bs, acc, tid);

    #pragma unroll
    for (int i = 0; i < 8; i++) {
        int m  = blockIdx.y * 128 + ty * 8 + i;
        int n0 = blockIdx.x * 128 + tx * 8;
        float2 c0 = up2(acc[i][0]), c1 = up2(acc[i][1]);
        float2 c2 = up2(acc[i][2]), c3 = up2(acc[i][3]);
        float4 v0 = make_float4(c0.x, c0.y, c1.x, c1.y);
        float4 v1 = make_float4(c2.x, c2.y, c3.x, c3.y);
        if (R) {
            float4 r0 = *(const float4*)(R + (size_t)m * N + n0);
            float4 r1 = *(const float4*)(R + (size_t)m * N + n0 + 4);
            v0.x += r0.x; v0.y += r0.y; v0.z += r0.z; v0.w += r0.w;
            v1.x += r1.x; v1.y += r1.y; v1.z += r1.z; v1.w += r1.w;
        }
        *(float4*)(C + (size_t)m * N + n0)     = v0;
        *(float4*)(C + (size_t)m * N + n0 + 4) = v1;
    }
}

// ---------------- fused QKV (raw, RoPE applied afterwards) ----------------
// grid (12, NTOK/128): bx 0-7 -> Q cols bx*128; 8-9 -> K; 10-11 -> V
__global__ __launch_bounds__(256)
void qkv2_k(const float* __restrict__ A,
            const float* __restrict__ Wq, const float* __restrict__ Wk,
            const float* __restrict__ Wv,
            float* __restrict__ qo, float* __restrict__ ko, float* __restrict__ vo) {
    __shared__ float As[16][128];
    __shared__ float Bs[16][128];
    int bx = blockIdx.x;
    const float* Bp; float* O; int N, colb;
    if (bx < 8)       { Bp = Wq; O = qo; N = 1024; colb = bx * 128; }
    else if (bx < 10) { Bp = Wk; O = ko; N = 256;  colb = (bx - 8)  * 128; }
    else              { Bp = Wv; O = vo; N = 256;  colb = (bx - 10) * 128; }

    int tid = threadIdx.x;
    int tx = tid & 15, ty = tid >> 4;
    const float* Ab = A + (size_t)blockIdx.y * 128 * HH;
    const float* Bb = Bp + colb;
    ull acc[8][4];
    #pragma unroll
    for (int i = 0; i < 8; i++)
        #pragma unroll
        for (int j = 0; j < 4; j++) acc[i][j] = 0ull;

    gemm128_body(Ab, Bb, HH, N, As, Bs, acc, tid);

    #pragma unroll
    for (int i = 0; i < 8; i++) {
        int m  = blockIdx.y * 128 + ty * 8 + i;
        int n0 = colb + tx * 8;
        float2 c0 = up2(acc[i][0]), c1 = up2(acc[i][1]);
        float2 c2 = up2(acc[i][2]), c3 = up2(acc[i][3]);
        *(float4*)(O + (size_t)m * N + n0)     = make_float4(c0.x, c0.y, c1.x, c1.y);
        *(float4*)(O + (size_t)m * N + n0 + 4) = make_float4(c2.x, c2.y, c3.x, c3.y);
    }
}

// ---------------- RoPE (in-place) ----------------
__global__ void rope_k(float* __restrict__ q, const float* __restrict__ cosp,
                       const float* __restrict__ sinp, int heads, int total) {
    int idx = blockIdx.x * blockDim.x + threadIdx.x;
    if (idx >= total) return;
    int d  = idx & 31;
    int t2 = idx >> 5;
    int hh = t2 % heads;
    int n  = t2 / heads;
    int t  = n & (TT - 1);
    float* p = q + ((size_t)n * heads + hh) * HDD;
    float c1 = cosp[t * HDD + d],      s1 = sinp[t * HDD + d];
    float c2 = cosp[t * HDD + d + 32], s2 = sinp[t * HDD + d + 32];
    float a = p[d], b = p[d + 32];
    p[d]      = a * c1 - b * s1;
    p[d + 32] = b * c2 + a * s2;
}

// ---------------- causal GQA attention (f32x2 online softmax) ----------------
__global__ __launch_bounds__(128)
void attn_k(const float* __restrict__ q, const float* __restrict__ k,
            const float* __restrict__ v, float* __restrict__ o) {
    __shared__ float Ks[64][HDD];
    __shared__ float Vs[64][HDD];
    int bh  = blockIdx.y;
    int b   = bh >> 4;
    int h   = bh & 15;
    int kvh = h >> 2;
    int bx  = gridDim.x - 1 - blockIdx.x;
    int qi  = bx * 128 + threadIdx.x;

    ull q2[32], o2[32];
    const ull* qp = (const ull*)(q + (((size_t)(b * TT + qi)) * NHD + h) * HDD);
    ull sc = pk2(0.125f, 0.125f);
    #pragma unroll
    for (int d = 0; d < 32; d++) { q2[d] = qp[d]; mul2(q2[d], sc); o2[d] = 0ull; }
    float m = -1e30f, l = 0.f;

    int qmax = bx * 128 + 127;
    for (int j0 = 0; j0 <= qmax; j0 += 64) {
        __syncthreads();
        for (int e = threadIdx.x; e < 64 * (HDD / 4); e += 128) {
            int jj = e >> 4;
            int dd = (e & 15) * 4;
            size_t base = (((size_t)(b * TT + j0 + jj)) * NKVH + kvh) * HDD + dd;
            *(float4*)&Ks[jj][dd] = *(const float4*)(k + base);
            *(float4*)&Vs[jj][dd] = *(const float4*)(v + base);
        }
        __syncthreads();
        int jend = qi - j0 + 1;
        if (jend > 64) jend = 64;
        for (int jj = 0; jj < jend; jj++) {
            const ull* kr = (const ull*)Ks[jj];
            ull sA = 0ull, sB = 0ull, sC = 0ull, sD = 0ull;
            #pragma unroll
            for (int d = 0; d < 32; d += 4) {
                fma2(sA, q2[d],     kr[d]);
                fma2(sB, q2[d + 1], kr[d + 1]);
                fma2(sC, q2[d + 2], kr[d + 2]);
                fma2(sD, q2[d + 3], kr[d + 3]);
            }
            float2 fA = up2(sA), fB = up2(sB), fC = up2(sC), fD = up2(sD);
            float s = (fA.x + fA.y) + (fB.x + fB.y) + (fC.x + fC.y) + (fD.x + fD.y);
            if (s > m) {
                float fexp = __expf(m - s);
                ull f2 = pk2(fexp, fexp);
                l *= fexp;
                #pragma unroll
                for (int d = 0; d < 32; d++) mul2(o2[d], f2);
                m = s;
            }
            float p = __expf(s - m);
            l += p;
            ull p2 = pk2(p, p);
            const ull* vr = (const ull*)Vs[jj];
            #pragma unroll
            for (int d = 0; d < 32; d++) fma2(o2[d], p2, vr[d]);
        }
    }
    float invl = 1.f / l;
    ull il2 = pk2(invl, invl);
    ull* op = (ull*)(o + (((size_t)(b * TT + qi)) * NHD + h) * HDD);
    #pragma unroll
    for (int d = 0; d < 32; d++) { mul2(o2[d], il2); op[d] = o2[d]; }
}

// ---------------- legacy 64x64 SGEMM for router (N=64) ----------------
__global__ __launch_bounds__(256)
void sgemm_k(const float* __restrict__ A, const float* __restrict__ B,
             float* __restrict__ C, int M, int N, int K) {
    __shared__ ull   As2[16][64];
    __shared__ float Bs[16][64];
    int tid = threadIdx.x;
    int tx = tid & 15, ty = tid >> 4;
    const float* Ab = A + (size_t)blockIdx.y * 64 * K;
    const float* Bb = B + (size_t)blockIdx.x * 64;
    ull acc[4][2];
    #pragma unroll
    for (int i = 0; i < 4; i++) { acc[i][0] = 0ull; acc[i][1] = 0ull; }

    for (int k0 = 0; k0 < K; k0 += 16) {
        #pragma unroll
        for (int l = 0; l < 4; l++) {
            int idx = tid + l * 256;
            int m = idx >> 4, k = idx & 15;
            float v = Ab[(size_t)m * K + k0 + k];
            As2[k][m] = pk2(v, v);
        }
        #pragma unroll
        for (int l = 0; l < 4; l++) {
            int idx = tid + l * 256;
            int k = idx >> 6, n = idx & 63;
            Bs[k][n] = Bb[(size_t)(k0 + k) * N + n];
        }
        __syncthreads();
        #pragma unroll
        for (int k = 0; k < 16; k++) {
            const ull* brow = (const ull*)Bs[k];
            ull b0 = brow[tx * 2], b1 = brow[tx * 2 + 1];
            #pragma unroll
            for (int i = 0; i < 4; i++) {
                ull a2 = As2[k][ty * 4 + i];
                fma2(acc[i][0], a2, b0);
                fma2(acc[i][1], a2, b1);
            }
        }
        __syncthreads();
    }
    #pragma unroll
    for (int i = 0; i < 4; i++) {
        int m = blockIdx.y * 64 + ty * 4 + i;
        int nb = blockIdx.x * 64 + tx * 4;
        float2 c0 = up2(acc[i][0]), c1 = up2(acc[i][1]);
        *(float4*)(C + (size_t)m * N + nb) = make_float4(c0.x, c0.y, c1.x, c1.y);
    }
}

// ---------------- router top-8 select + expert scatter ----------------
__global__ void zero_cnt_k() {
    if (threadIdx.x < NE) g_cnt[threadIdx.x] = 0;
}

__global__ void topk_k(const float* __restrict__ logits) {
    int n = blockIdx.x * blockDim.x + threadIdx.x;
    if (n >= NTOK) return;
    float lg[NE];
    for (int e = 0; e < NE; e++) lg[e] = logits[(size_t)n * NE + e];
    int   ids[TOPK];
    float vals[TOPK];
    for (int kk = 0; kk < TOPK; kk++) {
        int best = 0; float bv = lg[0];
        for (int e = 1; e < NE; e++) if (lg[e] > bv) { bv = lg[e]; best = e; }
        ids[kk] = best; vals[kk] = bv; lg[best] = -1e30f;
    }
    float mx = vals[0], sum = 0.f;
    for (int kk = 0; kk < TOPK; kk++) { vals[kk] = __expf(vals[kk] - mx); sum += vals[kk]; }
    float inv = 1.f / sum;
    for (int kk = 0; kk < TOPK; kk++) {
        int e = ids[kk];
        int p = atomicAdd(&g_cnt[e], 1);
        g_tok[e * NTOK + p] = n;
        g_scr[e * NTOK + p] = vals[kk] * inv;
        g_slt[e * NTOK + p] = n * TOPK + kk;
    }
}

// ======== MoE: register-tiled, 16-token tiles, broadcast splats ========
// grid (x = tile, y = expert). 256 threads = tidN(128, 4 inter cols) x tidM(2, 8 tok)
__global__ __launch_bounds__(256)
void moe2_k(const float* __restrict__ f, const float* __restrict__ Wg,
            const float* __restrict__ Wu, const float* __restrict__ Wd,
            float* __restrict__ y) {
    __shared__ float Fs_t[64][16];   // [k][tok]
    __shared__ float Gs_t[NI][16];   // [i][tok], 32KB
    __shared__ int   toks[16];
    __shared__ float scs[16];
    __shared__ int   slts[16];

    int e  = blockIdx.y;
    int nt = g_cnt[e];
    int t0 = blockIdx.x * 16;
    if (t0 >= nt) return;

    int tid  = threadIdx.x;
    int tidN = tid & 127, tidM = tid >> 7;
    if (tid < 16) {
        int ti = t0 + tid;
        toks[tid] = (ti < nt) ? g_tok[e * NTOK + ti] : -1;
        scs[tid]  = (ti < nt) ? g_scr[e * NTOK + ti] : 0.f;
        slts[tid] = (ti < nt) ? g_slt[e * NTOK + ti] : -1;
    }
    __syncthreads();

    // ---- phase 1: gate + up (C[16,512] twice, K=1024) ----
    ull ag[8][2], au[8][2];
    #pragma unroll
    for (int t = 0; t < 8; t++) { ag[t][0] = ag[t][1] = au[t][0] = au[t][1] = 0ull; }

    const float* Wge = Wg + (size_t)e * HH * NI + 4 * tidN;
    const float* Wue = Wu + (size_t)e * HH * NI + 4 * tidN;
    int tokrow = tid >> 4, kc = (tid & 15) * 4;
    int tk = toks[tokrow];
    const float* frow = (tk >= 0) ? f + (size_t)tk * HH : 0;

    for (int h0 = 0; h0 < HH; h0 += 64) {
        float4 fv = frow ? *(const float4*)(frow + h0 + kc)
                         : make_float4(0.f, 0.f, 0.f, 0.f);
        __syncthreads();
        Fs_t[kc + 0][tokrow] = fv.x; Fs_t[kc + 1][tokrow] = fv.y;
        Fs_t[kc + 2][tokrow] = fv.z; Fs_t[kc + 3][tokrow] = fv.w;
        __syncthreads();
        #pragma unroll 2
        for (int k = 0; k < 64; k++) {
            float4 f0 = *(const float4*)&Fs_t[k][tidM * 8];
            float4 f1 = *(const float4*)&Fs_t[k][tidM * 8 + 4];
            ull s0 = pk2(f0.x, f0.x), s1 = pk2(f0.y, f0.y);
            ull s2 = pk2(f0.z, f0.z), s3 = pk2(f0.w, f0.w);
            ull s4 = pk2(f1.x, f1.x), s5 = pk2(f1.y, f1.y);
            ull s6 = pk2(f1.z, f1.z), s7 = pk2(f1.w, f1.w);
            ulonglong2 wg = *(const ulonglong2*)(Wge + (size_t)(h0 + k) * NI);
            ulonglong2 wu = *(const ulonglong2*)(Wue + (size_t)(h0 + k) * NI);
            #define GU(t, s) fma2(ag[t][0], s, wg.x); fma2(ag[t][1], s, wg.y); \
                             fma2(au[t][0], s, wu.x); fma2(au[t][1], s, wu.y);
            GU(0, s0) GU(1, s1) GU(2, s2) GU(3, s3)
            GU(4, s4) GU(5, s5) GU(6, s6) GU(7, s7)
            #undef GU
        }
    }
    __syncthreads();
    // ---- silu(g)*u -> Gs_t transposed ----
    #pragma unroll
    for (int t = 0; t < 8; t++) {
        int tok = tidM * 8 + t;
        float2 g0 = up2(ag[t][0]), g1 = up2(ag[t][1]);
        float2 u0 = up2(au[t][0]), u1 = up2(au[t][1]);
        Gs_t[4 * tidN + 0][tok] = g0.x / (1.f + __expf(-g0.x)) * u0.x;
        Gs_t[4 * tidN + 1][tok] = g0.y / (1.f + __expf(-g0.y)) * u0.y;
        Gs_t[4 * tidN + 2][tok] = g1.x / (1.f + __expf(-g1.x)) * u1.x;
        Gs_t[4 * tidN + 3][tok] = g1.y / (1.f + __expf(-g1.y)) * u1.y;
    }
    __syncthreads();

    // ---- phase 2: down (C[16,1024], K=512); thread = 8 tok x 8 cols ----
    ull acc[8][4];
    #pragma unroll
    for (int t = 0; t < 8; t++) { acc[t][0] = acc[t][1] = acc[t][2] = acc[t][3] = 0ull; }
    const float* Wde = Wd + (size_t)e * NI * HH + 8 * tidN;
    #pragma unroll 2
    for (int i = 0; i < NI; i++) {
        float4 g0 = *(const float4*)&Gs_t[i][tidM * 8];
        float4 g1 = *(const float4*)&Gs_t[i][tidM * 8 + 4];
        ull s0 = pk2(g0.x, g0.x), s1 = pk2(g0.y, g0.y);
        ull s2 = pk2(g0.z, g0.z), s3 = pk2(g0.w, g0.w);
        ull s4 = pk2(g1.x, g1.x), s5 = pk2(g1.y, g1.y);
        ull s6 = pk2(g1.z, g1.z), s7 = pk2(g1.w, g1.w);
        ulonglong2 w0 = *(const ulonglong2*)(Wde + (size_t)i * HH);
        ulonglong2 w1 = *(const ulonglong2*)(Wde + (size_t)i * HH + 4);
        #define DN(t, s) fma2(acc[t][0], s, w0.x); fma2(acc[t][1], s, w0.y); \
                         fma2(acc[t][2], s, w1.x); fma2(acc[t][3], s, w1.y);
        DN(0, s0) DN(1, s1) DN(2, s2) DN(3, s3)
        DN(4, s4) DN(5, s5) DN(6, s6) DN(7, s7)
        #undef DN
    }
    #pragma unroll
    for (int t = 0; t < 8; t++) {
        int idx  = tidM * 8 + t;
        int slot = slts[idx];
        if (slot < 0) continue;
        float s = scs[idx];
        float2 a0 = up2(acc[t][0]), a1 = up2(acc[t][1]);
        float2 a2 = up2(acc[t][2]), a3 = up2(acc[t][3]);
        float* op = y + (size_t)slot * HH + 8 * tidN;
        *(float4*)(op)     = make_float4(s * a0.x, s * a0.y, s * a1.x, s * a1.y);
        *(float4*)(op + 4) = make_float4(s * a2.x, s * a2.y, s * a3.x, s * a3.y);
    }
}

// ---------------- gather: out += sum_k y[(n,k)] ----------------
__global__ void gather_k(const float* __restrict__ y, float* __restrict__ out) {
    int n = blockIdx.x;
    int c = threadIdx.x * 4;
    const float* base = y + (size_t)n * TOPK * HH + c;
    float4 a = *(float4*)(out + (size_t)n * HH + c);
    #pragma unroll
    for (int kk = 0; kk < TOPK; kk++) {
        float4 yv = *(const float4*)(base + (size_t)kk * HH);
        a.x += yv.x; a.y += yv.y; a.z += yv.z; a.w += yv.w;
    }
    *(float4*)(out + (size_t)n * HH + c) = a;
}

// ---------------- launch ----------------
extern "C" void kernel_launch(void* const* d_in, const int* in_sizes, int n_in,
                              void* d_out, int out_size) {
    const float* x    = (const float*)d_in[0];
    const float* cosp = (const float*)d_in[1];
    const float* sinp = (const float*)d_in[2];
    const float* ln1w = (const float*)d_in[3];
    const float* ln2w = (const float*)d_in[4];
    const float* Wq   = (const float*)d_in[5];
    const float* Wk   = (const float*)d_in[6];
    const float* Wv   = (const float*)d_in[7];
    const float* Wo   = (const float*)d_in[8];
    const float* Wr   = (const float*)d_in[9];
    const float* Wg   = (const float*)d_in[10];
    const float* Wu   = (const float*)d_in[11];
    const float* Wd   = (const float*)d_in[12];

    float* out    = (float*)d_out;                       // [NTOK, HH]
    float* logits = (float*)d_out + (size_t)NTOK * HH;   // [NTOK, NE]

    float *hb, *qb, *kb, *vb, *ab, *fb, *yb;
    cudaGetSymbolAddress((void**)&hb, g_h);
    cudaGetSymbolAddress((void**)&qb, g_q);
    cudaGetSymbolAddress((void**)&kb, g_k);
    cudaGetSymbolAddress((void**)&vb, g_v);
    cudaGetSymbolAddress((void**)&ab, g_att);
    cudaGetSymbolAddress((void**)&fb, g_f);
    cudaGetSymbolAddress((void**)&yb, g_y);

    // 1. rmsnorm1
    rmsnorm_k<<<NTOK, 256>>>(x, ln1w, hb);
    // 2. fused QKV (raw)
    qkv2_k<<<dim3(12, NTOK / 128), 256>>>(hb, Wq, Wk, Wv, qb, kb, vb);
    // 3. RoPE
    {
        int tq = NTOK * NHD * 32;
        rope_k<<<(tq + 255) / 256, 256>>>(qb, cosp, sinp, NHD, tq);
        int tkn = NTOK * NKVH * 32;
        rope_k<<<(tkn + 255) / 256, 256>>>(kb, cosp, sinp, NKVH, tkn);
    }
    // 4. attention
    attn_k<<<dim3(TT / 128, BB * NHD), 128>>>(qb, kb, vb, ab);
    // 5. Wo + residual -> out
    sgemm2_k<<<dim3(HH / 128, NTOK / 128), 256>>>(ab, Wo, x, out, HH, HH);
    // 6. rmsnorm2
    rmsnorm_k<<<NTOK, 256>>>(out, ln2w, fb);
    // 7. router logits
    sgemm_k<<<dim3(1, NTOK / 64), 256>>>(fb, Wr, logits, NTOK, NE, HH);
    // 8-9. top-8 + scatter
    zero_cnt_k<<<1, 64>>>();
    topk_k<<<(NTOK + 255) / 256, 256>>>(logits);
    // 10. MoE -> per-slot scratch (x = tile so same-expert blocks are adjacent)
    moe2_k<<<dim3(NTOK / 16, NE), 256>>>(fb, Wg, Wu, Wd, yb);
    // 11. gather slots into out
    gather_k<<<NTOK, 256>>>(yb, out);
}

// round 9
// speedup vs baseline: 3.7247x; 3.7247x over previous
#include <cuda_runtime.h>
#include <math.h>
#include <stdint.h>

#define BB   2
#define TT   1024
#define HH   1024
#define NHD  16
#define NKVH 4
#define HDD  64
#define NE   64
#define TOPK 8
#define NI   512
#define NTOK (BB*TT)   // 2048
#define MT   32        // MoE token tile

typedef unsigned long long ull;

// ---------------- f32x2 helpers (attention) ----------------
__device__ __forceinline__ ull pk2(float a, float b) {
    ull r; asm("mov.b64 %0,{%1,%2};" : "=l"(r) : "f"(a), "f"(b)); return r;
}
__device__ __forceinline__ void fma2(ull& d, ull a, ull b) {
    asm("fma.rn.f32x2 %0,%1,%2,%0;" : "+l"(d) : "l"(a), "l"(b));
}
__device__ __forceinline__ void mul2(ull& d, ull a) {
    asm("mul.rn.f32x2 %0,%0,%1;" : "+l"(d) : "l"(a));
}
__device__ __forceinline__ float2 up2(ull v) {
    float2 f; asm("mov.b64 {%0,%1},%2;" : "=f"(f.x), "=f"(f.y) : "l"(v)); return f;
}

// ---------------- tf32 mma helpers ----------------
__device__ __forceinline__ void mma_tf32(float* d, const uint32_t* a, const uint32_t* b) {
    asm volatile(
        "mma.sync.aligned.m16n8k8.row.col.f32.tf32.tf32.f32 "
        "{%0,%1,%2,%3}, {%4,%5,%6,%7}, {%8,%9}, {%0,%1,%2,%3};"
        : "+f"(d[0]), "+f"(d[1]), "+f"(d[2]), "+f"(d[3])
        : "r"(a[0]), "r"(a[1]), "r"(a[2]), "r"(a[3]), "r"(b[0]), "r"(b[1]));
}
__device__ __forceinline__ uint32_t cvta_s(const void* p) {
    return (uint32_t)__cvta_generic_to_shared(p);
}
__device__ __forceinline__ void cp16(uint32_t s, const void* g) {
    asm volatile("cp.async.cg.shared.global [%0], [%1], 16;" :: "r"(s), "l"(g));
}
#define CP_COMMIT asm volatile("cp.async.commit_group;")
#define CP_WAIT0  asm volatile("cp.async.wait_group 0;")
#define CP_WAIT1  asm volatile("cp.async.wait_group 1;")

// ---------------- scratch (device globals) ----------
__device__ float g_h  [NTOK*HH];
__device__ float g_q  [NTOK*NHD*HDD];
__device__ float g_k  [NTOK*NKVH*HDD];
__device__ float g_v  [NTOK*NKVH*HDD];
__device__ float g_att[NTOK*NHD*HDD];
__device__ float g_f  [NTOK*HH];
__device__ float g_y  [(size_t)NTOK*TOPK*HH];
__device__ int   g_cnt[NE];
__device__ int   g_tok[NE*NTOK];
__device__ float g_scr[NE*NTOK];
__device__ int   g_slt[NE*NTOK];

// ---------------- rmsnorm ----------------
__global__ void rmsnorm_k(const float* __restrict__ x, const float* __restrict__ w,
                          float* __restrict__ o) {
    int row = blockIdx.x;
    const float* xr = x + (size_t)row * HH;
    float ss = 0.f;
    for (int i = threadIdx.x; i < HH; i += 256) { float v = xr[i]; ss += v * v; }
    __shared__ float red[256];
    red[threadIdx.x] = ss; __syncthreads();
    for (int s = 128; s > 0; s >>= 1) {
        if (threadIdx.x < s) red[threadIdx.x] += red[threadIdx.x + s];
        __syncthreads();
    }
    float inv = rsqrtf(red[0] * (1.0f / HH) + 1e-6f);
    float* op = o + (size_t)row * HH;
    for (int i = threadIdx.x; i < HH; i += 256) op[i] = xr[i] * inv * w[i];
}

// ======== 128x128 tf32 MMA GEMM core ========
// 256 threads = 8 warps, warp tile 32(m) x 64(n): warp_m = wid&3, warp_n = wid>>2.
// smem: A token-major [128][20] (pad4), B k-major [16][136] (pad8), double-buffered.

__device__ __forceinline__ void stageAB(int tid, int buf, int k0,
    const float* __restrict__ Ab, int K, const float* __restrict__ Bb, int N,
    float (*As)[128][20], float (*Bs)[16][136]) {
    #pragma unroll
    for (int i = 0; i < 2; i++) {
        int slot = tid + i * 256;
        int row = slot >> 2, seg = slot & 3;
        cp16(cvta_s(&As[buf][row][seg * 4]), Ab + (size_t)row * K + k0 + seg * 4);
    }
    #pragma unroll
    for (int i = 0; i < 2; i++) {
        int slot = tid + i * 256;
        int r = slot >> 5, c4 = (slot & 31) * 4;
        cp16(cvta_s(&Bs[buf][r][c4]), Bb + (size_t)(k0 + r) * N + c4);
    }
}

__device__ __forceinline__ void gemm128_mma(
    const float* __restrict__ Ab, int K, const float* __restrict__ Bb, int N,
    float (*As)[128][20], float (*Bs)[16][136],
    float acc[2][8][4], int tid)
{
    int lane = tid & 31, wid = tid >> 5;
    int wm = (wid & 3) * 32, wn = (wid >> 2) * 64;

    stageAB(tid, 0, 0, Ab, K, Bb, N, As, Bs);
    CP_COMMIT;
    int nit = K >> 4;
    for (int it = 0; it < nit; it++) {
        if (it + 1 < nit) {
            stageAB(tid, (it + 1) & 1, (it + 1) << 4, Ab, K, Bb, N, As, Bs);
            CP_COMMIT; CP_WAIT1;
        } else { CP_WAIT0; }
        __syncthreads();
        const float (*A1)[20]  = As[it & 1];
        const float (*B1)[136] = Bs[it & 1];
        #pragma unroll
        for (int k8 = 0; k8 < 16; k8 += 8) {
            int kk = k8 + (lane & 3);
            uint32_t af[2][4];
            #pragma unroll
            for (int t = 0; t < 2; t++) {
                int r = wm + t * 16 + (lane >> 2);
                af[t][0] = __float_as_uint(A1[r][kk]);
                af[t][1] = __float_as_uint(A1[r + 8][kk]);
                af[t][2] = __float_as_uint(A1[r][kk + 4]);
                af[t][3] = __float_as_uint(A1[r + 8][kk + 4]);
            }
            #pragma unroll
            for (int j = 0; j < 8; j++) {
                int c = wn + j * 8 + (lane >> 2);
                uint32_t bf[2];
                bf[0] = __float_as_uint(B1[kk][c]);
                bf[1] = __float_as_uint(B1[kk + 4][c]);
                mma_tf32(acc[0][j], af[0], bf);
                mma_tf32(acc[1][j], af[1], bf);
            }
        }
        __syncthreads();
    }
}

// ---------------- fused QKV (tf32 mma) ----------------
// grid (12, NTOK/128): bx 0-7 -> Q cols bx*128; 8,9 -> K; 10,11 -> V
__global__ __launch_bounds__(256)
void qkv_mma_k(const float* __restrict__ A,
               const float* __restrict__ Wq, const float* __restrict__ Wk,
               const float* __restrict__ Wv,
               float* __restrict__ qo, float* __restrict__ ko, float* __restrict__ vo) {
    __shared__ float As[2][128][20];
    __shared__ float Bs[2][16][136];
    int bx = blockIdx.x;
    const float* Bp; float* O; int N, colb;
    if (bx < 8)       { Bp = Wq; O = qo; N = 1024; colb = bx * 128; }
    else if (bx < 10) { Bp = Wk; O = ko; N = 256;  colb = (bx - 8)  * 128; }
    else              { Bp = Wv; O = vo; N = 256;  colb = (bx - 10) * 128; }

    int tid = threadIdx.x, lane = tid & 31, wid = tid >> 5;
    int wm = (wid & 3) * 32, wn = (wid >> 2) * 64;
    int mbase = blockIdx.y * 128;
    float acc[2][8][4];
    #pragma unroll
    for (int t = 0; t < 2; t++)
        #pragma unroll
        for (int j = 0; j < 8; j++)
            #pragma unroll
            for (int q = 0; q < 4; q++) acc[t][j][q] = 0.f;

    gemm128_mma(A + (size_t)mbase * HH, HH, Bp + colb, N, As, Bs, acc, tid);

    #pragma unroll
    for (int t = 0; t < 2; t++) {
        int r0 = mbase + wm + t * 16 + (lane >> 2);
        #pragma unroll
        for (int j = 0; j < 8; j++) {
            int c = colb + wn + j * 8 + 2 * (lane & 3);
            *(float2*)(O + (size_t)r0 * N + c)       = make_float2(acc[t][j][0], acc[t][j][1]);
            *(float2*)(O + (size_t)(r0 + 8) * N + c) = make_float2(acc[t][j][2], acc[t][j][3]);
        }
    }
}

// ---------------- Wo GEMM + residual (tf32 mma) ----------------
__global__ __launch_bounds__(256)
void wo_mma_k(const float* __restrict__ A, const float* __restrict__ B,
              const float* __restrict__ R, float* __restrict__ C) {
    __shared__ float As[2][128][20];
    __shared__ float Bs[2][16][136];
    int tid = threadIdx.x, lane = tid & 31, wid = tid >> 5;
    int wm = (wid & 3) * 32, wn = (wid >> 2) * 64;
    int mbase = blockIdx.y * 128, nbase = blockIdx.x * 128;
    float acc[2][8][4];
    #pragma unroll
    for (int t = 0; t < 2; t++)
        #pragma unroll
        for (int j = 0; j < 8; j++)
            #pragma unroll
            for (int q = 0; q < 4; q++) acc[t][j][q] = 0.f;

    gemm128_mma(A + (size_t)mbase * HH, HH, B + nbase, HH, As, Bs, acc, tid);

    #pragma unroll
    for (int t = 0; t < 2; t++) {
        int r0 = mbase + wm + t * 16 + (lane >> 2);
        #pragma unroll
        for (int j = 0; j < 8; j++) {
            int c = nbase + wn + j * 8 + 2 * (lane & 3);
            float2 x0 = *(const float2*)(R + (size_t)r0 * HH + c);
            float2 x1 = *(const float2*)(R + (size_t)(r0 + 8) * HH + c);
            *(float2*)(C + (size_t)r0 * HH + c) =
                make_float2(acc[t][j][0] + x0.x, acc[t][j][1] + x0.y);
            *(float2*)(C + (size_t)(r0 + 8) * HH + c) =
                make_float2(acc[t][j][2] + x1.x, acc[t][j][3] + x1.y);
        }
    }
}

// ---------------- RoPE (in-place) ----------------
__global__ void rope_k(float* __restrict__ q, const float* __restrict__ cosp,
                       const float* __restrict__ sinp, int heads, int total) {
    int idx = blockIdx.x * blockDim.x + threadIdx.x;
    if (idx >= total) return;
    int d  = idx & 31;
    int t2 = idx >> 5;
    int hh = t2 % heads;
    int n  = t2 / heads;
    int t  = n & (TT - 1);
    float* p = q + ((size_t)n * heads + hh) * HDD;
    float c1 = cosp[t * HDD + d],      s1 = sinp[t * HDD + d];
    float c2 = cosp[t * HDD + d + 32], s2 = sinp[t * HDD + d + 32];
    float a = p[d], b = p[d + 32];
    p[d]      = a * c1 - b * s1;
    p[d + 32] = b * c2 + a * s2;
}

// ---------------- causal GQA attention (f32x2 online softmax) ----------------
__global__ __launch_bounds__(128)
void attn_k(const float* __restrict__ q, const float* __restrict__ k,
            const float* __restrict__ v, float* __restrict__ o) {
    __shared__ float Ks[64][HDD];
    __shared__ float Vs[64][HDD];
    int bh  = blockIdx.y;
    int b   = bh >> 4;
    int h   = bh & 15;
    int kvh = h >> 2;
    int bx  = gridDim.x - 1 - blockIdx.x;
    int qi  = bx * 128 + threadIdx.x;

    ull q2[32], o2[32];
    const ull* qp = (const ull*)(q + (((size_t)(b * TT + qi)) * NHD + h) * HDD);
    ull sc = pk2(0.125f, 0.125f);
    #pragma unroll
    for (int d = 0; d < 32; d++) { q2[d] = qp[d]; mul2(q2[d], sc); o2[d] = 0ull; }
    float m = -1e30f, l = 0.f;

    int qmax = bx * 128 + 127;
    for (int j0 = 0; j0 <= qmax; j0 += 64) {
        __syncthreads();
        for (int e = threadIdx.x; e < 64 * (HDD / 4); e += 128) {
            int jj = e >> 4;
            int dd = (e & 15) * 4;
            size_t base = (((size_t)(b * TT + j0 + jj)) * NKVH + kvh) * HDD + dd;
            *(float4*)&Ks[jj][dd] = *(const float4*)(k + base);
            *(float4*)&Vs[jj][dd] = *(const float4*)(v + base);
        }
        __syncthreads();
        int jend = qi - j0 + 1;
        if (jend > 64) jend = 64;
        for (int jj = 0; jj < jend; jj++) {
            const ull* kr = (const ull*)Ks[jj];
            ull sA = 0ull, sB = 0ull, sC = 0ull, sD = 0ull;
            #pragma unroll
            for (int d = 0; d < 32; d += 4) {
                fma2(sA, q2[d],     kr[d]);
                fma2(sB, q2[d + 1], kr[d + 1]);
                fma2(sC, q2[d + 2], kr[d + 2]);
                fma2(sD, q2[d + 3], kr[d + 3]);
            }
            float2 fA = up2(sA), fB = up2(sB), fC = up2(sC), fD = up2(sD);
            float s = (fA.x + fA.y) + (fB.x + fB.y) + (fC.x + fC.y) + (fD.x + fD.y);
            if (s > m) {
                float fexp = __expf(m - s);
                ull f2 = pk2(fexp, fexp);
                l *= fexp;
                #pragma unroll
                for (int d = 0; d < 32; d++) mul2(o2[d], f2);
                m = s;
            }
            float p = __expf(s - m);
            l += p;
            ull p2 = pk2(p, p);
            const ull* vr = (const ull*)Vs[jj];
            #pragma unroll
            for (int d = 0; d < 32; d++) fma2(o2[d], p2, vr[d]);
        }
    }
    float invl = 1.f / l;
    ull il2 = pk2(invl, invl);
    ull* op = (ull*)(o + (((size_t)(b * TT + qi)) * NHD + h) * HDD);
    #pragma unroll
    for (int d = 0; d < 32; d++) { mul2(o2[d], il2); op[d] = o2[d]; }
}

// ---------------- router SGEMM (fp32, N=64) ----------------
__global__ __launch_bounds__(256)
void sgemm_k(const float* __restrict__ A, const float* __restrict__ B,
             float* __restrict__ C, int M, int N, int K) {
    __shared__ ull   As2[16][64];
    __shared__ float Bs[16][64];
    int tid = threadIdx.x;
    int tx = tid & 15, ty = tid >> 4;
    const float* Ab = A + (size_t)blockIdx.y * 64 * K;
    const float* Bb = B + (size_t)blockIdx.x * 64;
    ull acc[4][2];
    #pragma unroll
    for (int i = 0; i < 4; i++) { acc[i][0] = 0ull; acc[i][1] = 0ull; }

    for (int k0 = 0; k0 < K; k0 += 16) {
        #pragma unroll
        for (int l = 0; l < 4; l++) {
            int idx = tid + l * 256;
            int m = idx >> 4, k = idx & 15;
            float v = Ab[(size_t)m * K + k0 + k];
            As2[k][m] = pk2(v, v);
        }
        #pragma unroll
        for (int l = 0; l < 4; l++) {
            int idx = tid + l * 256;
            int k = idx >> 6, n = idx & 63;
            Bs[k][n] = Bb[(size_t)(k0 + k) * N + n];
        }
        __syncthreads();
        #pragma unroll
        for (int k = 0; k < 16; k++) {
            const ull* brow = (const ull*)Bs[k];
            ull b0 = brow[tx * 2], b1 = brow[tx * 2 + 1];
            #pragma unroll
            for (int i = 0; i < 4; i++) {
                ull a2 = As2[k][ty * 4 + i];
                fma2(acc[i][0], a2, b0);
                fma2(acc[i][1], a2, b1);
            }
        }
        __syncthreads();
    }
    #pragma unroll
    for (int i = 0; i < 4; i++) {
        int m = blockIdx.y * 64 + ty * 4 + i;
        int nb = blockIdx.x * 64 + tx * 4;
        float2 c0 = up2(acc[i][0]), c1 = up2(acc[i][1]);
        *(float4*)(C + (size_t)m * N + nb) = make_float4(c0.x, c0.y, c1.x, c1.y);
    }
}

// ---------------- router top-8 select + expert scatter ----------------
__global__ void zero_cnt_k() {
    if (threadIdx.x < NE) g_cnt[threadIdx.x] = 0;
}

__global__ void topk_k(const float* __restrict__ logits) {
    int n = blockIdx.x * blockDim.x + threadIdx.x;
    if (n >= NTOK) return;
    float lg[NE];
    for (int e = 0; e < NE; e++) lg[e] = logits[(size_t)n * NE + e];
    int   ids[TOPK];
    float vals[TOPK];
    for (int kk = 0; kk < TOPK; kk++) {
        int best = 0; float bv = lg[0];
        for (int e = 1; e < NE; e++) if (lg[e] > bv) { bv = lg[e]; best = e; }
        ids[kk] = best; vals[kk] = bv; lg[best] = -1e30f;
    }
    float mx = vals[0], sum = 0.f;
    for (int kk = 0; kk < TOPK; kk++) { vals[kk] = __expf(vals[kk] - mx); sum += vals[kk]; }
    float inv = 1.f / sum;
    for (int kk = 0; kk < TOPK; kk++) {
        int e = ids[kk];
        int p = atomicAdd(&g_cnt[e], 1);
        g_tok[e * NTOK + p] = n;
        g_scr[e * NTOK + p] = vals[kk] * inv;
        g_slt[e * NTOK + p] = n * TOPK + kk;
    }
}

// ======== MoE: tf32 mma, 32-token tiles, 2-phase, cp.async pipelined ========
// dyn smem (floats):
//  Ast [2][32][20]          @ 0        (1280)
//  Gs  [32][516]            @ 1280     (16512)
//  Wt  [2][16640]           @ 17792    (33280)  phase1: Bg[16][520] + Bu[16][520]; phase2: Bd[16][1032]
//  meta toks/scs/slts (32*3) @ 51072
#define MOE_SMEM_FLOATS (51072 + 96)

__global__ __launch_bounds__(256, 1)
void moe_mma_k(const float* __restrict__ f, const float* __restrict__ Wg,
               const float* __restrict__ Wu, const float* __restrict__ Wd,
               float* __restrict__ y) {
    extern __shared__ float sm[];
    float (*Ast)[32][20] = (float(*)[32][20])sm;
    float (*Gs)[516]     = (float(*)[516])(sm + 1280);
    float* Wt            = sm + 17792;           // [2][16640]
    int*   toks = (int*)(sm + 51072);
    float* scs  = (float*)(sm + 51072 + 32);
    int*   slts = (int*)(sm + 51072 + 64);

    int e  = blockIdx.y;
    int nt = g_cnt[e];
    int t0 = blockIdx.x * MT;
    if (t0 >= nt) return;

    int tid = threadIdx.x, lane = tid & 31, wid = tid >> 5;
    if (tid < MT) {
        int ti = t0 + tid;
        toks[tid] = (ti < nt) ? g_tok[e * NTOK + ti] : 0;
        scs[tid]  = (ti < nt) ? g_scr[e * NTOK + ti] : 0.f;
        slts[tid] = (ti < nt) ? g_slt[e * NTOK + ti] : -1;
    }
    __syncthreads();

    const float* Wge = Wg + (size_t)e * HH * NI;
    const float* Wue = Wu + (size_t)e * HH * NI;
    const float* Wde = Wd + (size_t)e * NI * HH;

    // ---------- phase 1: gate + up;  C[32, 512] x2, K = 1024 ----------
    // warp w: cols w*64 .. w*64+63 of both gate and up. 2 m-tiles, 8 n-tiles, 2 mats.
    float ag[2][8][4], au[2][8][4];
    #pragma unroll
    for (int t = 0; t < 2; t++)
        #pragma unroll
        for (int j = 0; j < 8; j++)
            #pragma unroll
            for (int q = 0; q < 4; q++) { ag[t][j][q] = 0.f; au[t][j][q] = 0.f; }

    // staging lambda-ish via macro
    #define STAGE1(buf, k0) do {                                              \
        if (tid < 128) {                                                      \
            int tok = tid >> 2, seg = tid & 3;                                \
            cp16(cvta_s(&Ast[buf][tok][seg * 4]),                             \
                 f + (size_t)toks[tok] * HH + (k0) + seg * 4);                \
        }                                                                     \
        float* bg = Wt + (buf) * 16640;                                       \
        float* bu = bg + 8320;                                                \
        _Pragma("unroll")                                                     \
        for (int i = 0; i < 8; i++) {                                         \
            int slot = tid + i * 256;                                         \
            int r = slot >> 7, c4 = (slot & 127) * 4;                         \
            cp16(cvta_s(bg + r * 520 + c4), Wge + (size_t)((k0) + r) * NI + c4); \
            cp16(cvta_s(bu + r * 520 + c4), Wue + (size_t)((k0) + r) * NI + c4); \
        }                                                                     \
    } while (0)

    STAGE1(0, 0); CP_COMMIT;
    for (int it = 0; it < 64; it++) {
        if (it + 1 < 64) { STAGE1((it + 1) & 1, (it + 1) << 4); CP_COMMIT; CP_WAIT1; }
        else { CP_WAIT0; }
        __syncthreads();
        int buf = it & 1;
        const float (*A1)[20] = Ast[buf];
        const float* bg = Wt + buf * 16640;
        const float* bu = bg + 8320;
        #pragma unroll
        for (int k8 = 0; k8 < 16; k8 += 8) {
            int kk = k8 + (lane & 3);
            uint32_t af[2][4];
            #pragma unroll
            for (int t = 0; t < 2; t++) {
                int r = t * 16 + (lane >> 2);
                af[t][0] = __float_as_uint(A1[r][kk]);
                af[t][1] = __float_as_uint(A1[r + 8][kk]);
                af[t][2] = __float_as_uint(A1[r][kk + 4]);
                af[t][3] = __float_as_uint(A1[r + 8][kk + 4]);
            }
            #pragma unroll
            for (int j = 0; j < 8; j++) {
                int c = wid * 64 + j * 8 + (lane >> 2);
                uint32_t bfg[2], bfu[2];
                bfg[0] = __float_as_uint(bg[kk * 520 + c]);
                bfg[1] = __float_as_uint(bg[(kk + 4) * 520 + c]);
                bfu[0] = __float_as_uint(bu[kk * 520 + c]);
                bfu[1] = __float_as_uint(bu[(kk + 4) * 520 + c]);
                mma_tf32(ag[0][j], af[0], bfg);
                mma_tf32(ag[1][j], af[1], bfg);
                mma_tf32(au[0][j], af[0], bfu);
                mma_tf32(au[1][j], af[1], bfu);
            }
        }
        __syncthreads();
    }

    // silu(g)*u -> Gs  (token-major [32][516])
    #pragma unroll
    for (int t = 0; t < 2; t++) {
        int r0 = t * 16 + (lane >> 2);
        #pragma unroll
        for (int j = 0; j < 8; j++) {
            int c = wid * 64 + j * 8 + 2 * (lane & 3);
            float gv0 = ag[t][j][0], gv1 = ag[t][j][1];
            float gv2 = ag[t][j][2], gv3 = ag[t][j][3];
            Gs[r0][c]         = gv0 / (1.f + __expf(-gv0)) * au[t][j][0];
            Gs[r0][c + 1]     = gv1 / (1.f + __expf(-gv1)) * au[t][j][1];
            Gs[r0 + 8][c]     = gv2 / (1.f + __expf(-gv2)) * au[t][j][2];
            Gs[r0 + 8][c + 1] = gv3 / (1.f + __expf(-gv3)) * au[t][j][3];
        }
    }
    __syncthreads();

    // ---------- phase 2: down;  C[32, 1024], K = 512 ----------
    // warp w: cols w*128 .. +127: 2 m-tiles x 16 n-tiles.
    float acc[2][16][4];
    #pragma unroll
    for (int t = 0; t < 2; t++)
        #pragma unroll
        for (int j = 0; j < 16; j++)
            #pragma unroll
            for (int q = 0; q < 4; q++) acc[t][j][q] = 0.f;

    #define STAGE2(buf, k0) do {                                              \
        float* bd = Wt + (buf) * 16640;                                       \
        _Pragma("unroll")                                                     \
        for (int i = 0; i < 16; i++) {                                        \
            int slot = tid + i * 256;                                         \
            int r = slot >> 8, c4 = (slot & 255) * 4;                         \
            cp16(cvta_s(bd + r * 1032 + c4), Wde + (size_t)((k0) + r) * HH + c4); \
        }                                                                     \
    } while (0)

    STAGE2(0, 0); CP_COMMIT;
    for (int it = 0; it < 32; it++) {
        if (it + 1 < 32) { STAGE2((it + 1) & 1, (it + 1) << 4); CP_COMMIT; CP_WAIT1; }
        else { CP_WAIT0; }
        __syncthreads();
        const float* bd = Wt + (it & 1) * 16640;
        int k0 = it << 4;
        #pragma unroll
        for (int k8 = 0; k8 < 16; k8 += 8) {
            int kk = k0 + k8 + (lane & 3);
            uint32_t af[2][4];
            #pragma unroll
            for (int t = 0; t < 2; t++) {
                int r = t * 16 + (lane >> 2);
                af[t][0] = __float_as_uint(Gs[r][kk]);
                af[t][1] = __float_as_uint(Gs[r + 8][kk]);
                af[t][2] = __float_as_uint(Gs[r][kk + 4]);
                af[t][3] = __float_as_uint(Gs[r + 8][kk + 4]);
            }
            int kl = k8 + (lane & 3);
            #pragma unroll
            for (int j = 0; j < 16; j++) {
                int c = wid * 128 + j * 8 + (lane >> 2);
                uint32_t bf[2];
                bf[0] = __float_as_uint(bd[kl * 1032 + c]);
                bf[1] = __float_as_uint(bd[(kl + 4) * 1032 + c]);
                mma_tf32(acc[0][j], af[0], bf);
                mma_tf32(acc[1][j], af[1], bf);
            }
        }
        __syncthreads();
    }

    // epilogue: scale by score, store to y slots
    #pragma unroll
    for (int t = 0; t < 2; t++) {
        int r0 = t * 16 + (lane >> 2);
        int s0 = slts[r0], s1 = slts[r0 + 8];
        float sc0 = scs[r0], sc1 = scs[r0 + 8];
        #pragma unroll
        for (int j = 0; j < 16; j++) {
            int c = wid * 128 + j * 8 + 2 * (lane & 3);
            if (s0 >= 0)
                *(float2*)(y + (size_t)s0 * HH + c) =
                    make_float2(sc0 * acc[t][j][0], sc0 * acc[t][j][1]);
            if (s1 >= 0)
                *(float2*)(y + (size_t)s1 * HH + c) =
                    make_float2(sc1 * acc[t][j][2], sc1 * acc[t][j][3]);
        }
    }
}

// ---------------- gather: out += sum_k y[(n,k)] ----------------
__global__ void gather_k(const float* __restrict__ y, float* __restrict__ out) {
    int n = blockIdx.x;
    int c = threadIdx.x * 4;
    const float* base = y + (size_t)n * TOPK * HH + c;
    float4 a = *(float4*)(out + (size_t)n * HH + c);
    #pragma unroll
    for (int kk = 0; kk < TOPK; kk++) {
        float4 yv = *(const float4*)(base + (size_t)kk * HH);
        a.x += yv.x; a.y += yv.y; a.z += yv.z; a.w += yv.w;
    }
    *(float4*)(out + (size_t)n * HH + c) = a;
}

// ---------------- launch ----------------
extern "C" void kernel_launch(void* const* d_in, const int* in_sizes, int n_in,
                              void* d_out, int out_size) {
    const float* x    = (const float*)d_in[0];
    const float* cosp = (const float*)d_in[1];
    const float* sinp = (const float*)d_in[2];
    const float* ln1w = (const float*)d_in[3];
    const float* ln2w = (const float*)d_in[4];
    const float* Wq   = (const float*)d_in[5];
    const float* Wk   = (const float*)d_in[6];
    const float* Wv   = (const float*)d_in[7];
    const float* Wo   = (const float*)d_in[8];
    const float* Wr   = (const float*)d_in[9];
    const float* Wg   = (const float*)d_in[10];
    const float* Wu   = (const float*)d_in[11];
    const float* Wd   = (const float*)d_in[12];

    float* out    = (float*)d_out;                       // [NTOK, HH]
    float* logits = (float*)d_out + (size_t)NTOK * HH;   // [NTOK, NE]

    float *hb, *qb, *kb, *vb, *ab, *fb, *yb;
    cudaGetSymbolAddress((void**)&hb, g_h);
    cudaGetSymbolAddress((void**)&qb, g_q);
    cudaGetSymbolAddress((void**)&kb, g_k);
    cudaGetSymbolAddress((void**)&vb, g_v);
    cudaGetSymbolAddress((void**)&ab, g_att);
    cudaGetSymbolAddress((void**)&fb, g_f);
    cudaGetSymbolAddress((void**)&yb, g_y);

    int moe_smem = MOE_SMEM_FLOATS * 4;
    cudaFuncSetAttribute(moe_mma_k, cudaFuncAttributeMaxDynamicSharedMemorySize, moe_smem);

    // 1. rmsnorm1
    rmsnorm_k<<<NTOK, 256>>>(x, ln1w, hb);
    // 2. fused QKV (tf32 mma)
    qkv_mma_k<<<dim3(12, NTOK / 128), 256>>>(hb, Wq, Wk, Wv, qb, kb, vb);
    // 3. RoPE
    {
        int tq = NTOK * NHD * 32;
        rope_k<<<(tq + 255) / 256, 256>>>(qb, cosp, sinp, NHD, tq);
        int tkn = NTOK * NKVH * 32;
        rope_k<<<(tkn + 255) / 256, 256>>>(kb, cosp, sinp, NKVH, tkn);
    }
    // 4. attention
    attn_k<<<dim3(TT / 128, BB * NHD), 128>>>(qb, kb, vb, ab);
    // 5. Wo + residual -> out
    wo_mma_k<<<dim3(HH / 128, NTOK / 128), 256>>>(ab, Wo, x, out);
    // 6. rmsnorm2
    rmsnorm_k<<<NTOK, 256>>>(out, ln2w, fb);
    // 7. router logits (fp32)
    sgemm_k<<<dim3(1, NTOK / 64), 256>>>(fb, Wr, logits, NTOK, NE, HH);
    // 8-9. top-8 + scatter
    zero_cnt_k<<<1, 64>>>();
    topk_k<<<(NTOK + 255) / 256, 256>>>(logits);
    // 10. MoE (tf32 mma) -> per-slot scratch
    moe_mma_k<<<dim3(NTOK / MT, NE), 256, moe_smem>>>(fb, Wg, Wu, Wd, yb);
    // 11. gather slots into out
    gather_k<<<NTOK, 256>>>(yb, out);
}